// round 6
// baseline (speedup 1.0000x reference)
#include <cuda_runtime.h>

// ModulatedConv2dWithUpsample: B=8, Cin=512, Cout=256, H=W=64, ks=3, wdim=512
// out: [8,256,128,128] fp32
//
// Math:
//   s[b,ci]     = style[b] . (mod_weight[ci] * 1/sqrt(512)) + mod_bias[ci]
//   demod[b,co] = rsqrt( scale^2 * sum_ci s^2 * sum_k weight^2 + 1e-8 ),  scale=1/sqrt(512*9)
//   up[p,q]     = sum_{ci,a,b} (scale*weight)[co,ci,a,b] * s[b,ci] * x[ci,(p-a)/2,(q-b)/2]  (parity)
//   final       = 4x4 blur([1,3,3,1] outer /16) of up, pad 1  -> 128x128
//
// Parity planes (P,Q in [0,64], zero-padded x):
//   EE[P,Q] = w00*x[P,Q]   + w02*x[P,Q-1] + w20*x[P-1,Q] + w22*x[P-1,Q-1]
//   EO[P,Q] = w01*x[P,Q]   + w21*x[P-1,Q]
//   OE[P,Q] = w10*x[P,Q]   + w12*x[P,Q-1]
//   OO[P,Q] = w11*x[P,Q]
// Blur (1D weights .25/.75/.75/.25 per parity):
//   u=2U  : .25*odd[U-1] + .75*even[U] + .75*odd[U] + .25*even[U+1]
//   u=2U+1: .25*even[U]  + .75*odd[U]  + .75*even[U+1] + .25*odd[U+1]

#define BB   8
#define CIN  512
#define COUT 256

// persistent scratch (__device__ globals: allocation-free rule)
__device__ float g_s[BB * CIN];
__device__ float g_demod[BB * COUT];
__device__ float g_wT[9 * CIN * COUT];        // [k][ci][co], scale applied
__device__ float g_wsq[COUT * CIN];           // sum_k (scale*w)^2
// planes: [cls(4)][b][co][P+1 (66 rows)][Q+2 (68 cols)] ; borders stay zero forever
__device__ float g_planes[(size_t)4 * BB * COUT * 66 * 68];

// ---------------------------------------------------------------- prep kernels

__global__ void k_style(const float* __restrict__ style,
                        const float* __restrict__ mw,
                        const float* __restrict__ mb) {
    int gt = blockIdx.x * blockDim.x + threadIdx.x;
    int wid = gt >> 5, lane = gt & 31;
    if (wid >= BB * CIN) return;
    int b = wid >> 9, ci = wid & (CIN - 1);
    const float* sp = style + b * 512;
    const float* wp = mw + ci * 512;
    float sum = 0.f;
    for (int t = lane; t < 512; t += 32) sum = fmaf(sp[t], wp[t], sum);
#pragma unroll
    for (int off = 16; off; off >>= 1) sum += __shfl_xor_sync(0xffffffffu, sum, off);
    if (lane == 0) g_s[wid] = sum * 0.04419417382415922f + mb[ci];  // 1/sqrt(512)
}

__global__ void k_wprep(const float* __restrict__ w) {
    int idx = blockIdx.x * blockDim.x + threadIdx.x;
    if (idx >= COUT * CIN) return;
    int co = idx >> 9, ci = idx & 511;
    const float sc = 0.014731391274719742f;  // 1/sqrt(512*9)
    float q = 0.f;
#pragma unroll
    for (int k = 0; k < 9; k++) {
        float wv = sc * w[idx * 9 + k];
        q = fmaf(wv, wv, q);
        g_wT[(k * CIN + ci) * COUT + co] = wv;
    }
    g_wsq[idx] = q;  // [co][ci]
}

__global__ void k_demod() {
    int gt = blockIdx.x * blockDim.x + threadIdx.x;
    int wid = gt >> 5, lane = gt & 31;
    if (wid >= BB * COUT) return;
    int b = wid >> 8, co = wid & 255;
    float sum = 0.f;
    for (int ci = lane; ci < CIN; ci += 32) {
        float sv = g_s[b * CIN + ci];
        sum = fmaf(sv * sv, g_wsq[co * CIN + ci], sum);
    }
#pragma unroll
    for (int off = 16; off; off >>= 1) sum += __shfl_xor_sync(0xffffffffu, sum, off);
    if (lane == 0) g_demod[wid] = rsqrtf(sum + 1e-8f);
}

// ---------------------------------------------------------------- main conv

#define CK 16

#define FMA4(A, W, X)                      \
    do {                                   \
        (A).x = fmaf((W).x, (X), (A).x);   \
        (A).y = fmaf((W).y, (X), (A).y);   \
        (A).z = fmaf((W).z, (X), (A).z);   \
        (A).w = fmaf((W).w, (X), (A).w);   \
    } while (0)

// grid: (45 = 9 P-tiles x 5 Q-tiles, 8 co-tiles, 8 b); block 256
// per CTA: 32 co x 8 P x 16 Q x 4 classes
// per thread: 4 co x (2x2 spatial) x 4 classes = 64 fp32 accumulators
__global__ __launch_bounds__(256, 2) void k_upconv(const float* __restrict__ x) {
    __shared__ float s_all[CIN];
    __shared__ float xs[CK][9][18];      // x' tile: rows P0-1..P0+7, cols Q0-1..Q0+15
    __shared__ float ws[9][CK][32];      // weights per tap

    const int b = blockIdx.z;
    const int cobase = blockIdx.y * 32;
    const int pt = blockIdx.x / 5, qt = blockIdx.x % 5;
    const int P0 = pt * 8, Q0 = qt * 16;
    const int tid = threadIdx.x;
    const int cog = tid >> 5;            // warp id -> co quad (uniform per warp)
    const int sp = tid & 31;
    const int pl = (sp >> 3) * 2;        // 0,2,4,6
    const int ql = (sp & 7) * 2;         // 0..14

    for (int i = tid; i < CIN; i += 256) s_all[i] = g_s[b * CIN + i];

    float4 acc[4][2][2];
#pragma unroll
    for (int c = 0; c < 4; c++)
#pragma unroll
        for (int pi = 0; pi < 2; pi++)
#pragma unroll
            for (int qi = 0; qi < 2; qi++)
                acc[c][pi][qi] = make_float4(0.f, 0.f, 0.f, 0.f);

    for (int cb = 0; cb < CIN; cb += CK) {
        __syncthreads();
        // stage modulated input tile
        for (int e = tid; e < CK * 9 * 17; e += 256) {
            int ci = e / 153;
            int rem = e - ci * 153;
            int r = rem / 17;
            int c = rem - r * 17;
            int gi = P0 - 1 + r, gj = Q0 - 1 + c;
            float v = 0.f;
            if ((unsigned)gi < 64u && (unsigned)gj < 64u)
                v = x[((b * CIN + cb + ci) * 64 + gi) * 64 + gj] * s_all[cb + ci];
            xs[ci][r][c] = v;
        }
        // stage weights [k][ci][32co]
        for (int e = tid; e < 9 * CK * 32; e += 256) {
            int k = e / (CK * 32);
            int rem = e - k * (CK * 32);
            int ci = rem >> 5;
            int co = rem & 31;
            ws[k][ci][co] = g_wT[(k * CIN + cb + ci) * COUT + cobase + co];
        }
        __syncthreads();

#pragma unroll 4
        for (int ci = 0; ci < CK; ci++) {
            float xv[3][3];
#pragma unroll
            for (int rr = 0; rr < 3; rr++)
#pragma unroll
                for (int cc = 0; cc < 3; cc++)
                    xv[rr][cc] = xs[ci][pl + rr][ql + cc];
            float4 wq[9];
#pragma unroll
            for (int k = 0; k < 9; k++)
                wq[k] = *reinterpret_cast<const float4*>(&ws[k][ci][cog * 4]);
#pragma unroll
            for (int pi = 0; pi < 2; pi++)
#pragma unroll
                for (int qi = 0; qi < 2; qi++) {
                    float xc = xv[pi + 1][qi + 1];  // x[P,Q]
                    float xl = xv[pi + 1][qi];      // x[P,Q-1]
                    float xu = xv[pi][qi + 1];      // x[P-1,Q]
                    float xd = xv[pi][qi];          // x[P-1,Q-1]
                    FMA4(acc[0][pi][qi], wq[0], xc);  // EE: w00
                    FMA4(acc[0][pi][qi], wq[2], xl);  //     w02
                    FMA4(acc[0][pi][qi], wq[6], xu);  //     w20
                    FMA4(acc[0][pi][qi], wq[8], xd);  //     w22
                    FMA4(acc[1][pi][qi], wq[1], xc);  // EO: w01
                    FMA4(acc[1][pi][qi], wq[7], xu);  //     w21
                    FMA4(acc[2][pi][qi], wq[3], xc);  // OE: w10
                    FMA4(acc[2][pi][qi], wq[5], xl);  //     w12
                    FMA4(acc[3][pi][qi], wq[4], xc);  // OO: w11
                }
        }
    }

    float dm[4];
#pragma unroll
    for (int l = 0; l < 4; l++) dm[l] = g_demod[b * COUT + cobase + cog * 4 + l];

#pragma unroll
    for (int cls = 0; cls < 4; cls++) {
#pragma unroll
        for (int pi = 0; pi < 2; pi++) {
            int P = P0 + pl + pi;
            if (P > 64) continue;
            int Q = Q0 + ql;   // even
            if (Q > 64) continue;
            const float* a0 = reinterpret_cast<const float*>(&acc[cls][pi][0]);
            const float* a1 = reinterpret_cast<const float*>(&acc[cls][pi][1]);
#pragma unroll
            for (int l = 0; l < 4; l++) {
                int co = cobase + cog * 4 + l;
                size_t base = ((((size_t)cls * BB + b) * COUT + co) * 66 + (P + 1)) * 68 + (Q + 2);
                float v0 = a0[l] * dm[l];
                if (Q < 64) {
                    float v1 = a1[l] * dm[l];
                    *reinterpret_cast<float2*>(&g_planes[base]) = make_float2(v0, v1);  // 8B aligned
                } else {
                    g_planes[base] = v0;
                }
            }
        }
    }
}

// ---------------------------------------------------------------- blur epilogue

// grid: (128 u, 256 co, 8 b), block 128 (v). Row-combine into smem, then 4 LDS/out.
__global__ void k_blur(float* __restrict__ out) {
    __shared__ float R[2][68];  // R[q-parity][Qc+1], row-blurred
    const int u = blockIdx.x, co = blockIdx.y, b = blockIdx.z;
    const int tid = threadIdx.x;
    const int U = u >> 1, pu = u & 1;
    int rP[4], rcls[4];  // rcls = p-parity * 2
    const float rw[4] = {0.25f, 0.75f, 0.75f, 0.25f};
    if (pu == 0) {
        rcls[0] = 2; rP[0] = U - 1;
        rcls[1] = 0; rP[1] = U;
        rcls[2] = 2; rP[2] = U;
        rcls[3] = 0; rP[3] = U + 1;
    } else {
        rcls[0] = 0; rP[0] = U;
        rcls[1] = 2; rP[1] = U;
        rcls[2] = 0; rP[2] = U + 1;
        rcls[3] = 2; rP[3] = U + 1;
    }
    for (int idx = tid; idx < 2 * 66; idx += 128) {
        int pq = idx / 66;
        int qi = idx - pq * 66;  // col index qi+1 in plane
        float a = 0.f;
#pragma unroll
        for (int r = 0; r < 4; r++) {
            size_t off = ((((size_t)(rcls[r] + pq) * BB + b) * COUT + co) * 66 + (rP[r] + 1)) * 68 + (qi + 1);
            a = fmaf(rw[r], g_planes[off], a);
        }
        R[pq][qi] = a;
    }
    __syncthreads();
    int v = tid;
    int V = v >> 1, pv = v & 1;
    float res;
    if (pv == 0)
        res = 0.25f * R[1][V] + 0.75f * R[0][V + 1] + 0.75f * R[1][V + 1] + 0.25f * R[0][V + 2];
    else
        res = 0.25f * R[0][V + 1] + 0.75f * R[1][V + 1] + 0.75f * R[0][V + 2] + 0.25f * R[1][V + 2];
    out[(((size_t)b * COUT + co) * 128 + u) * 128 + v] = res;
}

// ---------------------------------------------------------------- launch

extern "C" void kernel_launch(void* const* d_in, const int* in_sizes, int n_in,
                              void* d_out, int out_size) {
    (void)in_sizes; (void)n_in; (void)out_size;
    const float* input      = (const float*)d_in[0];  // [8,512,64,64]
    const float* style      = (const float*)d_in[1];  // [8,512]
    const float* weight     = (const float*)d_in[2];  // [1,256,512,3,3]
    const float* mod_weight = (const float*)d_in[3];  // [512,512]
    const float* mod_bias   = (const float*)d_in[4];  // [512]
    float* out = (float*)d_out;                       // [8,256,128,128]

    k_style<<<512, 256>>>(style, mod_weight, mod_bias);
    k_wprep<<<512, 256>>>(weight);
    k_demod<<<256, 256>>>();
    dim3 g1(45, 8, 8);
    k_upconv<<<g1, 256>>>(input);
    dim3 g2(128, 256, 8);
    k_blur<<<g2, 128>>>(out);
}

// round 9
// speedup vs baseline: 1.0001x; 1.0001x over previous
#include <cuda_runtime.h>

// ModulatedConv2dWithUpsample: B=8, Cin=512, Cout=256, H=W=64, ks=3, wdim=512
// out: [8,256,128,128] fp32
//
// Math:
//   s[b,ci]     = style[b] . (mod_weight[ci] * 1/sqrt(512)) + mod_bias[ci]
//   demod[b,co] = rsqrt( scale^2 * sum_ci s^2 * sum_k weight^2 + 1e-8 ),  scale=1/sqrt(512*9)
//   up[p,q]     = sum_{ci,a,b} (scale*weight)[co,ci,a,b] * s[b,ci] * x[ci,(p-a)/2,(q-b)/2]  (parity)
//   final       = 4x4 blur([1,3,3,1] outer /16) of up, pad 1  -> 128x128
//
// Parity planes (P,Q in [0,64], zero-padded x):
//   EE[P,Q] = w00*x[P,Q]   + w02*x[P,Q-1] + w20*x[P-1,Q] + w22*x[P-1,Q-1]
//   EO[P,Q] = w01*x[P,Q]   + w21*x[P-1,Q]
//   OE[P,Q] = w10*x[P,Q]   + w12*x[P,Q-1]
//   OO[P,Q] = w11*x[P,Q]
// Blur (1D weights .25/.75/.75/.25 per parity):
//   u=2U  : .25*odd[U-1] + .75*even[U] + .75*odd[U] + .25*even[U+1]
//   u=2U+1: .25*even[U]  + .75*odd[U]  + .75*even[U+1] + .25*odd[U+1]

#define BB   8
#define CIN  512
#define COUT 256

// persistent scratch (__device__ globals: allocation-free rule)
__device__ float g_s[BB * CIN];
__device__ float g_demod[BB * COUT];
__device__ float g_wT[9 * CIN * COUT];        // [k][ci][co], scale applied
__device__ float g_wsq[COUT * CIN];           // sum_k (scale*w)^2
// planes: [cls(4)][b][co][P+1 (66 rows)][Q+2 (68 cols)] ; borders stay zero forever
__device__ float g_planes[(size_t)4 * BB * COUT * 66 * 68];

// ---------------------------------------------------------------- prep kernels

__global__ void k_style(const float* __restrict__ style,
                        const float* __restrict__ mw,
                        const float* __restrict__ mb) {
    int gt = blockIdx.x * blockDim.x + threadIdx.x;
    int wid = gt >> 5, lane = gt & 31;
    if (wid >= BB * CIN) return;
    int b = wid >> 9, ci = wid & (CIN - 1);
    const float* sp = style + b * 512;
    const float* wp = mw + ci * 512;
    float sum = 0.f;
    for (int t = lane; t < 512; t += 32) sum = fmaf(sp[t], wp[t], sum);
#pragma unroll
    for (int off = 16; off; off >>= 1) sum += __shfl_xor_sync(0xffffffffu, sum, off);
    if (lane == 0) g_s[wid] = sum * 0.04419417382415922f + mb[ci];  // 1/sqrt(512)
}

__global__ void k_wprep(const float* __restrict__ w) {
    int idx = blockIdx.x * blockDim.x + threadIdx.x;
    if (idx >= COUT * CIN) return;
    int co = idx >> 9, ci = idx & 511;
    const float sc = 0.014731391274719742f;  // 1/sqrt(512*9)
    float q = 0.f;
#pragma unroll
    for (int k = 0; k < 9; k++) {
        float wv = sc * w[idx * 9 + k];
        q = fmaf(wv, wv, q);
        g_wT[(k * CIN + ci) * COUT + co] = wv;
    }
    g_wsq[idx] = q;  // [co][ci]
}

__global__ void k_demod() {
    int gt = blockIdx.x * blockDim.x + threadIdx.x;
    int wid = gt >> 5, lane = gt & 31;
    if (wid >= BB * COUT) return;
    int b = wid >> 8, co = wid & 255;
    float sum = 0.f;
    for (int ci = lane; ci < CIN; ci += 32) {
        float sv = g_s[b * CIN + ci];
        sum = fmaf(sv * sv, g_wsq[co * CIN + ci], sum);
    }
#pragma unroll
    for (int off = 16; off; off >>= 1) sum += __shfl_xor_sync(0xffffffffu, sum, off);
    if (lane == 0) g_demod[wid] = rsqrtf(sum + 1e-8f);
}

// ---------------------------------------------------------------- main conv

#define CK 16

#define FMA4(A, W, X)                      \
    do {                                   \
        (A).x = fmaf((W).x, (X), (A).x);   \
        (A).y = fmaf((W).y, (X), (A).y);   \
        (A).z = fmaf((W).z, (X), (A).z);   \
        (A).w = fmaf((W).w, (X), (A).w);   \
    } while (0)

// grid: (45 = 9 P-tiles x 5 Q-tiles, 8 co-tiles, 8 b); block 256
// per CTA: 32 co x 8 P x 16 Q x 4 classes
// per thread: 4 co x (2x2 spatial) x 4 classes = 64 fp32 accumulators
__global__ __launch_bounds__(256, 2) void k_upconv(const float* __restrict__ x) {
    __shared__ float s_all[CIN];
    __shared__ float xs[CK][9][18];      // x' tile: rows P0-1..P0+7, cols Q0-1..Q0+15
    __shared__ float ws[9][CK][32];      // weights per tap

    const int b = blockIdx.z;
    const int cobase = blockIdx.y * 32;
    const int pt = blockIdx.x / 5, qt = blockIdx.x % 5;
    const int P0 = pt * 8, Q0 = qt * 16;
    const int tid = threadIdx.x;
    const int cog = tid >> 5;            // warp id -> co quad (uniform per warp)
    const int sp = tid & 31;
    const int pl = (sp >> 3) * 2;        // 0,2,4,6
    const int ql = (sp & 7) * 2;         // 0..14

    for (int i = tid; i < CIN; i += 256) s_all[i] = g_s[b * CIN + i];

    float4 acc[4][2][2];
#pragma unroll
    for (int c = 0; c < 4; c++)
#pragma unroll
        for (int pi = 0; pi < 2; pi++)
#pragma unroll
            for (int qi = 0; qi < 2; qi++)
                acc[c][pi][qi] = make_float4(0.f, 0.f, 0.f, 0.f);

    for (int cb = 0; cb < CIN; cb += CK) {
        __syncthreads();
        // stage modulated input tile
        for (int e = tid; e < CK * 9 * 17; e += 256) {
            int ci = e / 153;
            int rem = e - ci * 153;
            int r = rem / 17;
            int c = rem - r * 17;
            int gi = P0 - 1 + r, gj = Q0 - 1 + c;
            float v = 0.f;
            if ((unsigned)gi < 64u && (unsigned)gj < 64u)
                v = x[((b * CIN + cb + ci) * 64 + gi) * 64 + gj] * s_all[cb + ci];
            xs[ci][r][c] = v;
        }
        // stage weights [k][ci][32co]
        for (int e = tid; e < 9 * CK * 32; e += 256) {
            int k = e / (CK * 32);
            int rem = e - k * (CK * 32);
            int ci = rem >> 5;
            int co = rem & 31;
            ws[k][ci][co] = g_wT[(k * CIN + cb + ci) * COUT + cobase + co];
        }
        __syncthreads();

#pragma unroll 4
        for (int ci = 0; ci < CK; ci++) {
            float xv[3][3];
#pragma unroll
            for (int rr = 0; rr < 3; rr++)
#pragma unroll
                for (int cc = 0; cc < 3; cc++)
                    xv[rr][cc] = xs[ci][pl + rr][ql + cc];
            float4 wq[9];
#pragma unroll
            for (int k = 0; k < 9; k++)
                wq[k] = *reinterpret_cast<const float4*>(&ws[k][ci][cog * 4]);
#pragma unroll
            for (int pi = 0; pi < 2; pi++)
#pragma unroll
                for (int qi = 0; qi < 2; qi++) {
                    float xc = xv[pi + 1][qi + 1];  // x[P,Q]
                    float xl = xv[pi + 1][qi];      // x[P,Q-1]
                    float xu = xv[pi][qi + 1];      // x[P-1,Q]
                    float xd = xv[pi][qi];          // x[P-1,Q-1]
                    FMA4(acc[0][pi][qi], wq[0], xc);  // EE: w00
                    FMA4(acc[0][pi][qi], wq[2], xl);  //     w02
                    FMA4(acc[0][pi][qi], wq[6], xu);  //     w20
                    FMA4(acc[0][pi][qi], wq[8], xd);  //     w22
                    FMA4(acc[1][pi][qi], wq[1], xc);  // EO: w01
                    FMA4(acc[1][pi][qi], wq[7], xu);  //     w21
                    FMA4(acc[2][pi][qi], wq[3], xc);  // OE: w10
                    FMA4(acc[2][pi][qi], wq[5], xl);  //     w12
                    FMA4(acc[3][pi][qi], wq[4], xc);  // OO: w11
                }
        }
    }

    float dm[4];
#pragma unroll
    for (int l = 0; l < 4; l++) dm[l] = g_demod[b * COUT + cobase + cog * 4 + l];

#pragma unroll
    for (int cls = 0; cls < 4; cls++) {
#pragma unroll
        for (int pi = 0; pi < 2; pi++) {
            int P = P0 + pl + pi;
            if (P > 64) continue;
            int Q = Q0 + ql;   // even
            if (Q > 64) continue;
            const float* a0 = reinterpret_cast<const float*>(&acc[cls][pi][0]);
            const float* a1 = reinterpret_cast<const float*>(&acc[cls][pi][1]);
#pragma unroll
            for (int l = 0; l < 4; l++) {
                int co = cobase + cog * 4 + l;
                size_t base = ((((size_t)cls * BB + b) * COUT + co) * 66 + (P + 1)) * 68 + (Q + 2);
                float v0 = a0[l] * dm[l];
                if (Q < 64) {
                    float v1 = a1[l] * dm[l];
                    *reinterpret_cast<float2*>(&g_planes[base]) = make_float2(v0, v1);  // 8B aligned
                } else {
                    g_planes[base] = v0;
                }
            }
        }
    }
}

// ---------------------------------------------------------------- blur epilogue

// grid: (128 u, 256 co, 8 b), block 128 (v). Row-combine into smem, then 4 LDS/out.
__global__ void k_blur(float* __restrict__ out) {
    __shared__ float R[2][68];  // R[q-parity][Qc+1], row-blurred
    const int u = blockIdx.x, co = blockIdx.y, b = blockIdx.z;
    const int tid = threadIdx.x;
    const int U = u >> 1, pu = u & 1;
    int rP[4], rcls[4];  // rcls = p-parity * 2
    const float rw[4] = {0.25f, 0.75f, 0.75f, 0.25f};
    if (pu == 0) {
        rcls[0] = 2; rP[0] = U - 1;
        rcls[1] = 0; rP[1] = U;
        rcls[2] = 2; rP[2] = U;
        rcls[3] = 0; rP[3] = U + 1;
    } else {
        rcls[0] = 0; rP[0] = U;
        rcls[1] = 2; rP[1] = U;
        rcls[2] = 0; rP[2] = U + 1;
        rcls[3] = 2; rP[3] = U + 1;
    }
    for (int idx = tid; idx < 2 * 66; idx += 128) {
        int pq = idx / 66;
        int qi = idx - pq * 66;  // col index qi+1 in plane
        float a = 0.f;
#pragma unroll
        for (int r = 0; r < 4; r++) {
            size_t off = ((((size_t)(rcls[r] + pq) * BB + b) * COUT + co) * 66 + (rP[r] + 1)) * 68 + (qi + 1);
            a = fmaf(rw[r], g_planes[off], a);
        }
        R[pq][qi] = a;
    }
    __syncthreads();
    int v = tid;
    int V = v >> 1, pv = v & 1;
    float res;
    if (pv == 0)
        res = 0.25f * R[1][V] + 0.75f * R[0][V + 1] + 0.75f * R[1][V + 1] + 0.25f * R[0][V + 2];
    else
        res = 0.25f * R[0][V + 1] + 0.75f * R[1][V + 1] + 0.75f * R[0][V + 2] + 0.25f * R[1][V + 2];
    out[(((size_t)b * COUT + co) * 128 + u) * 128 + v] = res;
}

// ---------------------------------------------------------------- launch

extern "C" void kernel_launch(void* const* d_in, const int* in_sizes, int n_in,
                              void* d_out, int out_size) {
    (void)in_sizes; (void)n_in; (void)out_size;
    const float* input      = (const float*)d_in[0];  // [8,512,64,64]
    const float* style      = (const float*)d_in[1];  // [8,512]
    const float* weight     = (const float*)d_in[2];  // [1,256,512,3,3]
    const float* mod_weight = (const float*)d_in[3];  // [512,512]
    const float* mod_bias   = (const float*)d_in[4];  // [512]
    float* out = (float*)d_out;                       // [8,256,128,128]

    k_style<<<512, 256>>>(style, mod_weight, mod_bias);
    k_wprep<<<512, 256>>>(weight);
    k_demod<<<256, 256>>>();
    dim3 g1(45, 8, 8);
    k_upconv<<<g1, 256>>>(input);
    dim3 g2(128, 256, 8);
    k_blur<<<g2, 128>>>(out);
}